// round 4
// baseline (speedup 1.0000x reference)
#include <cuda_runtime.h>

#define N_NODES   100000
#define N_EDGES   1600000
#define D         128
#define N_GRAPHS  512
#define N_CLASSES 10
#define GEMM_ROWS 16
#define K_CHUNK   32

// -------- scratch: __device__ globals, referenced ONLY inside device code --------
__device__ float g_h[N_NODES * D];      // h = x @ W
__device__ float g_agg[N_NODES * D];    // aggregated messages
__device__ float g_x[N_NODES * D];      // layer activations (ping-pong)
__device__ float g_dinv[N_NODES];       // 1/sqrt(deg)
__device__ float g_norm[N_EDGES];       // dinv[src]*dinv[dst]
__device__ float g_sums[N_GRAPHS * D];  // pooling sums
__device__ float g_cnts[N_GRAPHS];      // pooling counts

// ---------------------------------------------------------------
__global__ __launch_bounds__(256) void k_init_deg() {
    int i = blockIdx.x * blockDim.x + threadIdx.x;
    if (i < N_NODES) g_dinv[i] = 1.0f;   // self-loop
}

__global__ __launch_bounds__(256) void k_count_deg(const int* __restrict__ dst) {
    int e = blockIdx.x * blockDim.x + threadIdx.x;
    if (e < N_EDGES) atomicAdd(&g_dinv[dst[e]], 1.0f);
}

__global__ __launch_bounds__(256) void k_finish_dinv() {
    int i = blockIdx.x * blockDim.x + threadIdx.x;
    if (i < N_NODES) g_dinv[i] = rsqrtf(g_dinv[i]);
}

__global__ __launch_bounds__(256) void k_edge_norm(const int* __restrict__ src,
                                                   const int* __restrict__ dst) {
    int e = blockIdx.x * blockDim.x + threadIdx.x;
    if (e < N_EDGES) g_norm[e] = g_dinv[src[e]] * g_dinv[dst[e]];
}

// ---------------------------------------------------------------
// g_h[n, :] = src_x[n, :] @ W   where src_x = (SRC==0 ? xext : g_x)
// 256 threads: thread = (row-half, col). 16 rows x 128 cols per block.
// 8 named scalar accumulators -> no lmem possible. Static shared 18KB.
template <int SRC>
__global__ __launch_bounds__(256) void k_gemm(const float* __restrict__ xext,
                                              const float* __restrict__ W) {
    __shared__ float Ws[K_CHUNK * D];         // 16 KB
    __shared__ float Xs[GEMM_ROWS * K_CHUNK]; // 2 KB
    const int tid = threadIdx.x;              // 0..255
    const int col = tid & 127;                // output column
    const int rh  = tid >> 7;                 // row half (0 or 1)
    const int row0 = blockIdx.x * GEMM_ROWS;

    const float* __restrict__ xsrc = (SRC == 0) ? xext : g_x;

    float a0 = 0.f, a1 = 0.f, a2 = 0.f, a3 = 0.f;
    float a4 = 0.f, a5 = 0.f, a6 = 0.f, a7 = 0.f;

    const float4* x4 = (const float4*)xsrc;
    const float4* W4 = (const float4*)W;
    float4* Ws4 = (float4*)Ws;
    float4* Xs4 = (float4*)Xs;

    for (int kb = 0; kb < D / K_CHUNK; kb++) {
        __syncthreads();
        // W chunk: 32 rows x 128 cols = 1024 float4; 256 threads x 4, coalesced.
        #pragma unroll
        for (int i = 0; i < 4; i++)
            Ws4[tid + i * 256] = W4[kb * (K_CHUNK * D / 4) + tid + i * 256];
        // X chunk: 16 rows x 32 cols = 128 float4; threads 0..127, one each.
        if (tid < 128) {
            int r  = tid >> 3;                // 0..15
            int c4 = tid & 7;                 // 0..7
            Xs4[tid] = x4[(size_t)(row0 + r) * (D / 4) + kb * (K_CHUNK / 4) + c4];
        }
        __syncthreads();

        const float* xr = &Xs[rh * 8 * K_CHUNK];
        #pragma unroll
        for (int k = 0; k < K_CHUNK; k++) {
            float w = Ws[k * D + col];
            a0 += xr[0 * K_CHUNK + k] * w;
            a1 += xr[1 * K_CHUNK + k] * w;
            a2 += xr[2 * K_CHUNK + k] * w;
            a3 += xr[3 * K_CHUNK + k] * w;
            a4 += xr[4 * K_CHUNK + k] * w;
            a5 += xr[5 * K_CHUNK + k] * w;
            a6 += xr[6 * K_CHUNK + k] * w;
            a7 += xr[7 * K_CHUNK + k] * w;
        }
    }

    float* hp = &g_h[(size_t)(row0 + rh * 8) * D + col];
    hp[0 * D] = a0; hp[1 * D] = a1; hp[2 * D] = a2; hp[3 * D] = a3;
    hp[4 * D] = a4; hp[5 * D] = a5; hp[6 * D] = a6; hp[7 * D] = a7;
}

// g_agg[i,:] = g_h[i,:] * dinv[i]^2   (self-loop; initializes agg, no memset)
__global__ __launch_bounds__(256) void k_selfloop(void) {
    int idx = blockIdx.x * blockDim.x + threadIdx.x;     // over N*D/4
    if (idx >= N_NODES * D / 4) return;
    int node = idx / (D / 4);
    float dv = g_dinv[node];
    float d2 = dv * dv;
    float4 v = ((const float4*)g_h)[idx];
    v.x *= d2; v.y *= d2; v.z *= d2; v.w *= d2;
    ((float4*)g_agg)[idx] = v;
}

// warp per edge: g_agg[dst,:] += g_h[src,:] * g_norm[e]
__global__ __launch_bounds__(256) void k_scatter(const int* __restrict__ src,
                                                 const int* __restrict__ dst) {
    int w = (blockIdx.x * blockDim.x + threadIdx.x) >> 5;
    int lane = threadIdx.x & 31;
    if (w >= N_EDGES) return;
    int s = __ldg(&src[w]);
    int d = __ldg(&dst[w]);
    float nrm = g_norm[w];
    float4 v = *(const float4*)(g_h + (size_t)s * D + lane * 4);
    float* a = g_agg + (size_t)d * D + lane * 4;
    atomicAdd(a + 0, v.x * nrm);
    atomicAdd(a + 1, v.y * nrm);
    atomicAdd(a + 2, v.z * nrm);
    atomicAdd(a + 3, v.w * nrm);
}

// g_x = relu(g_agg + b)
__global__ __launch_bounds__(256) void k_bias_relu(const float* __restrict__ b) {
    int idx = blockIdx.x * blockDim.x + threadIdx.x;     // over N*D/4
    if (idx >= N_NODES * D / 4) return;
    int c4 = idx % (D / 4);
    float4 bb = ((const float4*)b)[c4];
    float4 v = ((const float4*)g_agg)[idx];
    v.x = fmaxf(v.x + bb.x, 0.f);
    v.y = fmaxf(v.y + bb.y, 0.f);
    v.z = fmaxf(v.z + bb.z, 0.f);
    v.w = fmaxf(v.w + bb.w, 0.f);
    ((float4*)g_x)[idx] = v;
}

// ---------------------------------------------------------------
__global__ __launch_bounds__(256) void k_zero_pool() {
    int i = blockIdx.x * blockDim.x + threadIdx.x;
    if (i < N_GRAPHS * D) g_sums[i] = 0.f;
    if (i < N_GRAPHS) g_cnts[i] = 0.f;
}

// warp per node: g_sums[batch[i],:] += g_x[i,:];  g_cnts[batch[i]] += 1
__global__ __launch_bounds__(256) void k_pool(const int* __restrict__ batch) {
    int node = (blockIdx.x * blockDim.x + threadIdx.x) >> 5;
    int lane = threadIdx.x & 31;
    if (node >= N_NODES) return;
    int b = __ldg(&batch[node]);
    float4 v = *(const float4*)(g_x + (size_t)node * D + lane * 4);
    float* sp = g_sums + (size_t)b * D + lane * 4;
    atomicAdd(sp + 0, v.x);
    atomicAdd(sp + 1, v.y);
    atomicAdd(sp + 2, v.z);
    atomicAdd(sp + 3, v.w);
    if (lane == 0) atomicAdd(&g_cnts[b], 1.0f);
}

// out[g, c] = (g_sums[g,:]/cnt) @ Wc[:, c] + bc[c]
__global__ __launch_bounds__(128) void k_classify(const float* __restrict__ Wc,
                                                  const float* __restrict__ bc,
                                                  float* __restrict__ out) {
    __shared__ float s[N_CLASSES];
    int g = blockIdx.x;
    int tid = threadIdx.x;   // 128 = feature dim
    if (tid < N_CLASSES) s[tid] = 0.f;
    __syncthreads();
    float cnt = fmaxf(g_cnts[g], 1.0f);
    float p = g_sums[(size_t)g * D + tid] / cnt;
    #pragma unroll
    for (int c = 0; c < N_CLASSES; c++)
        atomicAdd(&s[c], p * Wc[tid * N_CLASSES + c]);
    __syncthreads();
    if (tid < N_CLASSES) out[g * N_CLASSES + tid] = s[tid] + bc[tid];
}

// ---------------------------------------------------------------
extern "C" void kernel_launch(void* const* d_in, const int* in_sizes, int n_in,
                              void* d_out, int out_size) {
    const float* x       = (const float*)d_in[0];
    const int*   e_src   = (const int*)d_in[1];
    const int*   e_dst   = (const int*)d_in[2];
    const int*   batch   = (const int*)d_in[3];
    const float* W0 = (const float*)d_in[4];  const float* b0 = (const float*)d_in[5];
    const float* W1 = (const float*)d_in[6];  const float* b1 = (const float*)d_in[7];
    const float* W2 = (const float*)d_in[8];  const float* b2 = (const float*)d_in[9];
    const float* Wc = (const float*)d_in[10]; const float* bc = (const float*)d_in[11];
    float* out = (float*)d_out;

    const int NB_N   = (N_NODES + 255) / 256;
    const int NB_E   = (N_EDGES + 255) / 256;
    const int NB_ND4 = (N_NODES * D / 4 + 255) / 256;
    const int NB_EW  = (N_EDGES * 32 + 255) / 256;      // warp per edge
    const int NB_NW  = (N_NODES * 32 + 255) / 256;      // warp per node
    const int NB_G   = (N_GRAPHS + 1) * D / 256 + 1;

    // degree + edge norms (shared by all layers)
    k_init_deg<<<NB_N, 256>>>();
    k_count_deg<<<NB_E, 256>>>(e_dst);
    k_finish_dinv<<<NB_N, 256>>>();
    k_edge_norm<<<NB_E, 256>>>(e_src, e_dst);

    const int gemm_grid = N_NODES / GEMM_ROWS;   // 6250, exact

    // ---- layer 0: x -> g_x
    k_gemm<0><<<gemm_grid, 256>>>(x, W0);
    k_selfloop<<<NB_ND4, 256>>>();
    k_scatter<<<NB_EW, 256>>>(e_src, e_dst);
    k_bias_relu<<<NB_ND4, 256>>>(b0);

    // ---- layer 1: g_x -> g_x
    k_gemm<1><<<gemm_grid, 256>>>(nullptr, W1);
    k_selfloop<<<NB_ND4, 256>>>();
    k_scatter<<<NB_EW, 256>>>(e_src, e_dst);
    k_bias_relu<<<NB_ND4, 256>>>(b1);

    // ---- layer 2: g_x -> g_x
    k_gemm<1><<<gemm_grid, 256>>>(nullptr, W2);
    k_selfloop<<<NB_ND4, 256>>>();
    k_scatter<<<NB_EW, 256>>>(e_src, e_dst);
    k_bias_relu<<<NB_ND4, 256>>>(b2);

    // ---- global mean pool + classifier
    k_zero_pool<<<NB_G, 256>>>();
    k_pool<<<NB_NW, 256>>>(batch);
    k_classify<<<N_GRAPHS, 128>>>(Wc, bc, out);
}

// round 7
// speedup vs baseline: 2.5494x; 2.5494x over previous
#include <cuda_runtime.h>

#define N_NODES   100000
#define N_EDGES   1600000
#define D         128
#define N_GRAPHS  512
#define N_CLASSES 10
#define GEMM_ROWS 16
#define K_CHUNK   32
#define SCAN_B    512
#define N_SCANBLK ((N_NODES + SCAN_B - 1) / SCAN_B)   // 196

// -------- scratch: __device__ globals, referenced ONLY inside device code --------
__device__ float g_h[N_NODES * D];        // h = x @ W
__device__ float g_x[N_NODES * D];        // layer activations (ping-pong)
__device__ float g_dinv[N_NODES];         // 1/sqrt(deg)
__device__ int   g_deg[N_NODES];          // in-degree (no self-loop)
__device__ int   g_cnt[N_NODES];          // fill cursors
__device__ int   g_rowex[N_NODES];        // block-local exclusive scan
__device__ int   g_row[N_NODES + 1];      // CSR row offsets (by dst)
__device__ int   g_bsum[N_SCANBLK];       // per-block scan sums
__device__ int   g_boff[N_SCANBLK];       // scanned block offsets
__device__ int   g_csr_src[N_EDGES];      // CSR column indices (src nodes)
__device__ float g_csr_nrm[N_EDGES];      // per-edge norm dinv[s]*dinv[d]
__device__ float g_sums[N_GRAPHS * D];    // pooling sums
__device__ float g_cnts[N_GRAPHS];        // pooling counts

// ---------------------------------------------------------------
__global__ __launch_bounds__(256) void k_init() {
    int i = blockIdx.x * blockDim.x + threadIdx.x;
    if (i < N_NODES) { g_deg[i] = 0; g_cnt[i] = 0; }
}

__global__ __launch_bounds__(256) void k_count_deg(const int* __restrict__ dst) {
    int e = blockIdx.x * blockDim.x + threadIdx.x;
    if (e < N_EDGES) atomicAdd(&g_deg[dst[e]], 1);
}

__global__ __launch_bounds__(256) void k_finish_dinv() {
    int i = blockIdx.x * blockDim.x + threadIdx.x;
    if (i < N_NODES) g_dinv[i] = rsqrtf((float)g_deg[i] + 1.0f);
}

// ---- exclusive scan of g_deg -> g_row (3 stages) ----
__global__ __launch_bounds__(SCAN_B) void k_scan1() {
    __shared__ int s[SCAN_B];
    int tid = threadIdx.x;
    int gid = blockIdx.x * SCAN_B + tid;
    int v = (gid < N_NODES) ? g_deg[gid] : 0;
    s[tid] = v;
    __syncthreads();
    #pragma unroll
    for (int off = 1; off < SCAN_B; off <<= 1) {
        int t = (tid >= off) ? s[tid - off] : 0;
        __syncthreads();
        s[tid] += t;
        __syncthreads();
    }
    if (gid < N_NODES) g_rowex[gid] = s[tid] - v;   // exclusive
    if (tid == SCAN_B - 1) g_bsum[blockIdx.x] = s[tid];
}

__global__ __launch_bounds__(32) void k_scan2() {
    if (threadIdx.x == 0) {
        int run = 0;
        for (int b = 0; b < N_SCANBLK; b++) { g_boff[b] = run; run += g_bsum[b]; }
        g_row[N_NODES] = run;   // == N_EDGES
    }
}

__global__ __launch_bounds__(256) void k_scan3() {
    int i = blockIdx.x * blockDim.x + threadIdx.x;
    if (i < N_NODES) g_row[i] = g_rowex[i] + g_boff[i / SCAN_B];
}

// fill CSR: for each edge, place (src, norm) into dst's row
__global__ __launch_bounds__(256) void k_fill(const int* __restrict__ src,
                                              const int* __restrict__ dst) {
    int e = blockIdx.x * blockDim.x + threadIdx.x;
    if (e >= N_EDGES) return;
    int s = src[e], d = dst[e];
    int idx = g_row[d] + atomicAdd(&g_cnt[d], 1);
    g_csr_src[idx] = s;
    g_csr_nrm[idx] = g_dinv[s] * g_dinv[d];
}

// ---------------------------------------------------------------
// g_h[n, :] = src_x[n, :] @ W   where src_x = (SRC==0 ? xext : g_x)
// 256 threads: thread = (row-half, col). 16 rows x 128 cols per block.
template <int SRC>
__global__ __launch_bounds__(256) void k_gemm(const float* __restrict__ xext,
                                              const float* __restrict__ W) {
    __shared__ float Ws[K_CHUNK * D];         // 16 KB
    __shared__ float Xs[GEMM_ROWS * K_CHUNK]; // 2 KB
    const int tid = threadIdx.x;              // 0..255
    const int col = tid & 127;                // output column
    const int rh  = tid >> 7;                 // row half (0 or 1)
    const int row0 = blockIdx.x * GEMM_ROWS;

    const float* __restrict__ xsrc = (SRC == 0) ? xext : g_x;

    float a0 = 0.f, a1 = 0.f, a2 = 0.f, a3 = 0.f;
    float a4 = 0.f, a5 = 0.f, a6 = 0.f, a7 = 0.f;

    const float4* x4 = (const float4*)xsrc;
    const float4* W4 = (const float4*)W;
    float4* Ws4 = (float4*)Ws;
    float4* Xs4 = (float4*)Xs;

    for (int kb = 0; kb < D / K_CHUNK; kb++) {
        __syncthreads();
        #pragma unroll
        for (int i = 0; i < 4; i++)
            Ws4[tid + i * 256] = W4[kb * (K_CHUNK * D / 4) + tid + i * 256];
        if (tid < 128) {
            int r  = tid >> 3;
            int c4 = tid & 7;
            Xs4[tid] = x4[(size_t)(row0 + r) * (D / 4) + kb * (K_CHUNK / 4) + c4];
        }
        __syncthreads();

        const float* xr = &Xs[rh * 8 * K_CHUNK];
        #pragma unroll
        for (int k = 0; k < K_CHUNK; k++) {
            float w = Ws[k * D + col];
            a0 += xr[0 * K_CHUNK + k] * w;
            a1 += xr[1 * K_CHUNK + k] * w;
            a2 += xr[2 * K_CHUNK + k] * w;
            a3 += xr[3 * K_CHUNK + k] * w;
            a4 += xr[4 * K_CHUNK + k] * w;
            a5 += xr[5 * K_CHUNK + k] * w;
            a6 += xr[6 * K_CHUNK + k] * w;
            a7 += xr[7 * K_CHUNK + k] * w;
        }
    }

    float* hp = &g_h[(size_t)(row0 + rh * 8) * D + col];
    hp[0 * D] = a0; hp[1 * D] = a1; hp[2 * D] = a2; hp[3 * D] = a3;
    hp[4 * D] = a4; hp[5 * D] = a5; hp[6 * D] = a6; hp[7 * D] = a7;
}

// ---------------------------------------------------------------
// Fused aggregation: warp per node.
// g_x[n,:] = relu( dinv[n]^2 * h[n,:] + sum_{j in row(n)} nrm[j]*h[src[j],:] + b )
__global__ __launch_bounds__(256) void k_gather(const float* __restrict__ b) {
    int node = (blockIdx.x * blockDim.x + threadIdx.x) >> 5;
    int lane = threadIdx.x & 31;
    if (node >= N_NODES) return;

    const float4* h4 = (const float4*)g_h;
    int beg = g_row[node];
    int end = g_row[node + 1];

    float dv = g_dinv[node];
    float d2 = dv * dv;
    float4 acc = h4[(size_t)node * 32 + lane];
    acc.x *= d2; acc.y *= d2; acc.z *= d2; acc.w *= d2;

    // 2-way manual pipelining for MLP on the dependent index->row loads
    int j = beg;
    for (; j + 1 < end; j += 2) {
        int   s0 = __ldg(&g_csr_src[j]),   s1 = __ldg(&g_csr_src[j + 1]);
        float w0 = __ldg(&g_csr_nrm[j]),   w1 = __ldg(&g_csr_nrm[j + 1]);
        float4 v0 = h4[(size_t)s0 * 32 + lane];
        float4 v1 = h4[(size_t)s1 * 32 + lane];
        acc.x += v0.x * w0; acc.y += v0.y * w0; acc.z += v0.z * w0; acc.w += v0.w * w0;
        acc.x += v1.x * w1; acc.y += v1.y * w1; acc.z += v1.z * w1; acc.w += v1.w * w1;
    }
    if (j < end) {
        int   s0 = __ldg(&g_csr_src[j]);
        float w0 = __ldg(&g_csr_nrm[j]);
        float4 v0 = h4[(size_t)s0 * 32 + lane];
        acc.x += v0.x * w0; acc.y += v0.y * w0; acc.z += v0.z * w0; acc.w += v0.w * w0;
    }

    float4 bb = ((const float4*)b)[lane];
    acc.x = fmaxf(acc.x + bb.x, 0.f);
    acc.y = fmaxf(acc.y + bb.y, 0.f);
    acc.z = fmaxf(acc.z + bb.z, 0.f);
    acc.w = fmaxf(acc.w + bb.w, 0.f);
    ((float4*)g_x)[(size_t)node * 32 + lane] = acc;
}

// ---------------------------------------------------------------
__global__ __launch_bounds__(256) void k_zero_pool() {
    int i = blockIdx.x * blockDim.x + threadIdx.x;
    if (i < N_GRAPHS * D) g_sums[i] = 0.f;
    if (i < N_GRAPHS) g_cnts[i] = 0.f;
}

__global__ __launch_bounds__(256) void k_pool(const int* __restrict__ batch) {
    int node = (blockIdx.x * blockDim.x + threadIdx.x) >> 5;
    int lane = threadIdx.x & 31;
    if (node >= N_NODES) return;
    int b = __ldg(&batch[node]);
    float4 v = ((const float4*)g_x)[(size_t)node * 32 + lane];
    float* sp = g_sums + (size_t)b * D + lane * 4;
    atomicAdd(sp + 0, v.x);
    atomicAdd(sp + 1, v.y);
    atomicAdd(sp + 2, v.z);
    atomicAdd(sp + 3, v.w);
    if (lane == 0) atomicAdd(&g_cnts[b], 1.0f);
}

__global__ __launch_bounds__(128) void k_classify(const float* __restrict__ Wc,
                                                  const float* __restrict__ bc,
                                                  float* __restrict__ out) {
    __shared__ float s[N_CLASSES];
    int g = blockIdx.x;
    int tid = threadIdx.x;   // 128 = feature dim
    if (tid < N_CLASSES) s[tid] = 0.f;
    __syncthreads();
    float cnt = fmaxf(g_cnts[g], 1.0f);
    float p = g_sums[(size_t)g * D + tid] / cnt;
    #pragma unroll
    for (int c = 0; c < N_CLASSES; c++)
        atomicAdd(&s[c], p * Wc[tid * N_CLASSES + c]);
    __syncthreads();
    if (tid < N_CLASSES) out[g * N_CLASSES + tid] = s[tid] + bc[tid];
}

// ---------------------------------------------------------------
extern "C" void kernel_launch(void* const* d_in, const int* in_sizes, int n_in,
                              void* d_out, int out_size) {
    const float* x       = (const float*)d_in[0];
    const int*   e_src   = (const int*)d_in[1];
    const int*   e_dst   = (const int*)d_in[2];
    const int*   batch   = (const int*)d_in[3];
    const float* W0 = (const float*)d_in[4];  const float* b0 = (const float*)d_in[5];
    const float* W1 = (const float*)d_in[6];  const float* b1 = (const float*)d_in[7];
    const float* W2 = (const float*)d_in[8];  const float* b2 = (const float*)d_in[9];
    const float* Wc = (const float*)d_in[10]; const float* bc = (const float*)d_in[11];
    float* out = (float*)d_out;

    const int NB_N  = (N_NODES + 255) / 256;
    const int NB_E  = (N_EDGES + 255) / 256;
    const int NB_NW = (N_NODES * 32 + 255) / 256;      // warp per node
    const int NB_G  = (N_GRAPHS + 1) * D / 256 + 1;

    // ---- build CSR by dst + dinv (amortized over 3 layers) ----
    k_init<<<NB_N, 256>>>();
    k_count_deg<<<NB_E, 256>>>(e_dst);
    k_finish_dinv<<<NB_N, 256>>>();
    k_scan1<<<N_SCANBLK, SCAN_B>>>();
    k_scan2<<<1, 32>>>();
    k_scan3<<<NB_N, 256>>>();
    k_fill<<<NB_E, 256>>>(e_src, e_dst);

    const int gemm_grid = N_NODES / GEMM_ROWS;   // 6250, exact

    // ---- layer 0 ----
    k_gemm<0><<<gemm_grid, 256>>>(x, W0);
    k_gather<<<NB_NW, 256>>>(b0);
    // ---- layer 1 ----
    k_gemm<1><<<gemm_grid, 256>>>(nullptr, W1);
    k_gather<<<NB_NW, 256>>>(b1);
    // ---- layer 2 ----
    k_gemm<1><<<gemm_grid, 256>>>(nullptr, W2);
    k_gather<<<NB_NW, 256>>>(b2);

    // ---- global mean pool + classifier ----
    k_zero_pool<<<NB_G, 256>>>();
    k_pool<<<NB_NW, 256>>>(batch);
    k_classify<<<N_GRAPHS, 128>>>(Wc, bc, out);
}

// round 9
// speedup vs baseline: 3.0344x; 1.1903x over previous
#include <cuda_runtime.h>
#include <cuda_bf16.h>
#include <mma.h>
using namespace nvcuda;

#define N_NODES   100000
#define N_EDGES   1600000
#define D         128
#define N_GRAPHS  512
#define N_CLASSES 10
#define SCAN_B    512
#define N_SCANBLK ((N_NODES + SCAN_B - 1) / SCAN_B)   // 196
#define M_BLK     64
#define KC        64
#define N_PAD     64          // row padding so the 1563-block GEMM grid needs no tail guards

// -------- scratch: __device__ globals, referenced ONLY inside device code --------
__device__ float          g_h[(N_NODES + N_PAD) * D];   // h = x @ W (fp32)
__device__ __nv_bfloat16  g_xh[(N_NODES + N_PAD) * D];  // activation hi (bf16)
__device__ __nv_bfloat16  g_xl[(N_NODES + N_PAD) * D];  // activation lo (bf16 residual)
__device__ __nv_bfloat16  g_wh[D * D];                  // weight hi
__device__ __nv_bfloat16  g_wl[D * D];                  // weight lo
__device__ float g_dinv[N_NODES];
__device__ int   g_deg[N_NODES];
__device__ int   g_cnt[N_NODES];
__device__ int   g_rowex[N_NODES];
__device__ int   g_row[N_NODES + 1];
__device__ int   g_bsum[N_SCANBLK];
__device__ int   g_boff[N_SCANBLK];
__device__ int   g_csr_src[N_EDGES];
__device__ float g_csr_nrm[N_EDGES];
__device__ float g_sums[N_GRAPHS * D];
__device__ float g_cnts[N_GRAPHS];

// ----------------- CSR build (unchanged from 809us version) -----------------
__global__ __launch_bounds__(256) void k_init() {
    int i = blockIdx.x * blockDim.x + threadIdx.x;
    if (i < N_NODES) { g_deg[i] = 0; g_cnt[i] = 0; }
}
__global__ __launch_bounds__(256) void k_count_deg(const int* __restrict__ dst) {
    int e = blockIdx.x * blockDim.x + threadIdx.x;
    if (e < N_EDGES) atomicAdd(&g_deg[dst[e]], 1);
}
__global__ __launch_bounds__(256) void k_finish_dinv() {
    int i = blockIdx.x * blockDim.x + threadIdx.x;
    if (i < N_NODES) g_dinv[i] = rsqrtf((float)g_deg[i] + 1.0f);
}
__global__ __launch_bounds__(SCAN_B) void k_scan1() {
    __shared__ int s[SCAN_B];
    int tid = threadIdx.x;
    int gid = blockIdx.x * SCAN_B + tid;
    int v = (gid < N_NODES) ? g_deg[gid] : 0;
    s[tid] = v;
    __syncthreads();
    #pragma unroll
    for (int off = 1; off < SCAN_B; off <<= 1) {
        int t = (tid >= off) ? s[tid - off] : 0;
        __syncthreads();
        s[tid] += t;
        __syncthreads();
    }
    if (gid < N_NODES) g_rowex[gid] = s[tid] - v;
    if (tid == SCAN_B - 1) g_bsum[blockIdx.x] = s[tid];
}
__global__ __launch_bounds__(32) void k_scan2() {
    if (threadIdx.x == 0) {
        int run = 0;
        for (int b = 0; b < N_SCANBLK; b++) { g_boff[b] = run; run += g_bsum[b]; }
        g_row[N_NODES] = run;
    }
}
__global__ __launch_bounds__(256) void k_scan3() {
    int i = blockIdx.x * blockDim.x + threadIdx.x;
    if (i < N_NODES) g_row[i] = g_rowex[i] + g_boff[i / SCAN_B];
}
__global__ __launch_bounds__(256) void k_fill(const int* __restrict__ src,
                                              const int* __restrict__ dst) {
    int e = blockIdx.x * blockDim.x + threadIdx.x;
    if (e >= N_EDGES) return;
    int s = src[e], d = dst[e];
    int idx = g_row[d] + atomicAdd(&g_cnt[d], 1);
    g_csr_src[idx] = s;
    g_csr_nrm[idx] = g_dinv[s] * g_dinv[d];
}

// ----------------- pooling setup -----------------
__global__ __launch_bounds__(256) void k_zero_pool() {
    int i = blockIdx.x * blockDim.x + threadIdx.x;
    if (i < N_GRAPHS * D) g_sums[i] = 0.f;
    if (i < N_GRAPHS) g_cnts[i] = 0.f;
}
__global__ __launch_bounds__(256) void k_count_batch(const int* __restrict__ batch) {
    int i = blockIdx.x * blockDim.x + threadIdx.x;
    if (i < N_NODES) atomicAdd(&g_cnts[batch[i]], 1.0f);
}

// ----------------- bf16 hi/lo conversions -----------------
__global__ __launch_bounds__(256) void k_cvt_x(const float* __restrict__ x) {
    int i = blockIdx.x * blockDim.x + threadIdx.x;
    if (i >= N_NODES * D) return;
    float v = x[i];
    __nv_bfloat16 h = __float2bfloat16(v);
    g_xh[i] = h;
    g_xl[i] = __float2bfloat16(v - __bfloat162float(h));
}
__global__ __launch_bounds__(256) void k_cvt_w(const float* __restrict__ W) {
    int i = blockIdx.x * blockDim.x + threadIdx.x;
    if (i >= D * D) return;
    float v = W[i];
    __nv_bfloat16 h = __float2bfloat16(v);
    g_wh[i] = h;
    g_wl[i] = __float2bfloat16(v - __bfloat162float(h));
}

// ----------------- tensor-core GEMM: h = X @ W via split-bf16, K=384 -----------------
// A' = [Xh | Xl | Xh], B' = [Wh ; Wh ; Wl]  =>  Xh@Wh + Xl@Wh + Xh@Wl ~= X@W (err ~2^-17)
// Block: 64 rows x 128 cols, 8 warps (2x4), each warp 32x32 = 2x2 wmma tiles.
__global__ __launch_bounds__(256) void k_gemm_tc() {
    __shared__ __nv_bfloat16 As[M_BLK][KC + 8];   // 64x72 (9216B)
    __shared__ __nv_bfloat16 Bs[KC][D + 8];       // 64x136 (17408B)
    const int tid = threadIdx.x;
    const int wid = tid >> 5;
    const int wm = wid & 1;       // 2 warps along M (32 rows each)
    const int wn = wid >> 1;      // 4 warps along N (32 cols each)
    const int row0 = blockIdx.x * M_BLK;

    wmma::fragment<wmma::accumulator, 16, 16, 16, float> acc[2][2];
    #pragma unroll
    for (int i = 0; i < 2; i++)
        #pragma unroll
        for (int j = 0; j < 2; j++)
            wmma::fill_fragment(acc[i][j], 0.0f);

    #pragma unroll
    for (int c = 0; c < 6; c++) {
        const int seg = c >> 1;                       // 0,1,2
        const __nv_bfloat16* Asrc = (seg == 1) ? g_xl : g_xh;
        const __nv_bfloat16* Bsrc = (seg == 2) ? g_wl : g_wh;
        const int acol = (c & 1) * KC;
        const int brow = (c & 1) * KC;

        __syncthreads();
        // A: 64x64 bf16, 4-elem (8B) vectors: 1024 groups / 256 thr = 4 each
        #pragma unroll
        for (int j = 0; j < 4; j++) {
            int idx = tid + j * 256;
            int r = idx >> 4, g = idx & 15;
            *(uint2*)&As[r][g * 4] =
                *(const uint2*)&Asrc[(size_t)(row0 + r) * D + acol + g * 4];
        }
        // B: 64x128 bf16: 2048 groups / 256 thr = 8 each
        #pragma unroll
        for (int j = 0; j < 8; j++) {
            int idx = tid + j * 256;
            int r = idx >> 5, g = idx & 31;
            *(uint2*)&Bs[r][g * 4] =
                *(const uint2*)&Bsrc[(size_t)(brow + r) * D + g * 4];
        }
        __syncthreads();

        #pragma unroll
        for (int kk = 0; kk < KC / 16; kk++) {
            wmma::fragment<wmma::matrix_a, 16, 16, 16, __nv_bfloat16, wmma::row_major> af[2];
            wmma::fragment<wmma::matrix_b, 16, 16, 16, __nv_bfloat16, wmma::row_major> bf[2];
            #pragma unroll
            for (int i = 0; i < 2; i++)
                wmma::load_matrix_sync(af[i], &As[wm * 32 + i * 16][kk * 16], KC + 8);
            #pragma unroll
            for (int j = 0; j < 2; j++)
                wmma::load_matrix_sync(bf[j], &Bs[kk * 16][wn * 32 + j * 16], D + 8);
            #pragma unroll
            for (int i = 0; i < 2; i++)
                #pragma unroll
                for (int j = 0; j < 2; j++)
                    wmma::mma_sync(acc[i][j], af[i], bf[j], acc[i][j]);
        }
    }

    #pragma unroll
    for (int i = 0; i < 2; i++)
        #pragma unroll
        for (int j = 0; j < 2; j++)
            wmma::store_matrix_sync(
                &g_h[(size_t)(row0 + wm * 32 + i * 16) * D + wn * 32 + j * 16],
                acc[i][j], D, wmma::mem_row_major);
}

// ----------------- fused aggregation (warp per node) -----------------
// act = relu(dinv^2 * h[n] + sum nrm*h[src] + b)
// LAST=0: emit bf16 hi/lo pair for next layer's GEMM.
// LAST=1: atomically accumulate into g_sums[batch[n]] (fused mean-pool).
template <int LAST>
__global__ __launch_bounds__(256) void k_gather(const float* __restrict__ b,
                                                const int* __restrict__ batch) {
    int node = (blockIdx.x * blockDim.x + threadIdx.x) >> 5;
    int lane = threadIdx.x & 31;
    if (node >= N_NODES) return;

    const float4* h4 = (const float4*)g_h;
    int beg = g_row[node];
    int end = g_row[node + 1];

    float dv = g_dinv[node];
    float d2 = dv * dv;
    float4 acc = h4[(size_t)node * 32 + lane];
    acc.x *= d2; acc.y *= d2; acc.z *= d2; acc.w *= d2;

    int j = beg;
    for (; j + 1 < end; j += 2) {
        int   s0 = __ldg(&g_csr_src[j]),   s1 = __ldg(&g_csr_src[j + 1]);
        float w0 = __ldg(&g_csr_nrm[j]),   w1 = __ldg(&g_csr_nrm[j + 1]);
        float4 v0 = h4[(size_t)s0 * 32 + lane];
        float4 v1 = h4[(size_t)s1 * 32 + lane];
        acc.x += v0.x * w0; acc.y += v0.y * w0; acc.z += v0.z * w0; acc.w += v0.w * w0;
        acc.x += v1.x * w1; acc.y += v1.y * w1; acc.z += v1.z * w1; acc.w += v1.w * w1;
    }
    if (j < end) {
        int   s0 = __ldg(&g_csr_src[j]);
        float w0 = __ldg(&g_csr_nrm[j]);
        float4 v0 = h4[(size_t)s0 * 32 + lane];
        acc.x += v0.x * w0; acc.y += v0.y * w0; acc.z += v0.z * w0; acc.w += v0.w * w0;
    }

    float4 bb = ((const float4*)b)[lane];
    acc.x = fmaxf(acc.x + bb.x, 0.f);
    acc.y = fmaxf(acc.y + bb.y, 0.f);
    acc.z = fmaxf(acc.z + bb.z, 0.f);
    acc.w = fmaxf(acc.w + bb.w, 0.f);

    if (LAST) {
        int bg = __ldg(&batch[node]);
        float* sp = g_sums + (size_t)bg * D + lane * 4;
        atomicAdd(sp + 0, acc.x);
        atomicAdd(sp + 1, acc.y);
        atomicAdd(sp + 2, acc.z);
        atomicAdd(sp + 3, acc.w);
    } else {
        __nv_bfloat16 hx = __float2bfloat16(acc.x);
        __nv_bfloat16 hy = __float2bfloat16(acc.y);
        __nv_bfloat16 hz = __float2bfloat16(acc.z);
        __nv_bfloat16 hw = __float2bfloat16(acc.w);
        __nv_bfloat162* xh2 = (__nv_bfloat162*)g_xh;
        __nv_bfloat162* xl2 = (__nv_bfloat162*)g_xl;
        size_t base = (size_t)node * 64 + lane * 2;
        xh2[base + 0] = __nv_bfloat162{hx, hy};
        xh2[base + 1] = __nv_bfloat162{hz, hw};
        xl2[base + 0] = __nv_bfloat162{
            __float2bfloat16(acc.x - __bfloat162float(hx)),
            __float2bfloat16(acc.y - __bfloat162float(hy))};
        xl2[base + 1] = __nv_bfloat162{
            __float2bfloat16(acc.z - __bfloat162float(hz)),
            __float2bfloat16(acc.w - __bfloat162float(hw))};
    }
}

// ----------------- classifier -----------------
__global__ __launch_bounds__(128) void k_classify(const float* __restrict__ Wc,
                                                  const float* __restrict__ bc,
                                                  float* __restrict__ out) {
    __shared__ float s[N_CLASSES];
    int g = blockIdx.x;
    int tid = threadIdx.x;   // 128 = feature dim
    if (tid < N_CLASSES) s[tid] = 0.f;
    __syncthreads();
    float cnt = fmaxf(g_cnts[g], 1.0f);
    float p = g_sums[(size_t)g * D + tid] / cnt;
    #pragma unroll
    for (int c = 0; c < N_CLASSES; c++)
        atomicAdd(&s[c], p * Wc[tid * N_CLASSES + c]);
    __syncthreads();
    if (tid < N_CLASSES) out[g * N_CLASSES + tid] = s[tid] + bc[tid];
}

// ---------------------------------------------------------------
extern "C" void kernel_launch(void* const* d_in, const int* in_sizes, int n_in,
                              void* d_out, int out_size) {
    const float* x       = (const float*)d_in[0];
    const int*   e_src   = (const int*)d_in[1];
    const int*   e_dst   = (const int*)d_in[2];
    const int*   batch   = (const int*)d_in[3];
    const float* W0 = (const float*)d_in[4];  const float* b0 = (const float*)d_in[5];
    const float* W1 = (const float*)d_in[6];  const float* b1 = (const float*)d_in[7];
    const float* W2 = (const float*)d_in[8];  const float* b2 = (const float*)d_in[9];
    const float* Wc = (const float*)d_in[10]; const float* bc = (const float*)d_in[11];
    float* out = (float*)d_out;

    const int NB_N  = (N_NODES + 255) / 256;
    const int NB_E  = (N_EDGES + 255) / 256;
    const int NB_NW = (N_NODES * 32 + 255) / 256;          // warp per node
    const int NB_G  = (N_GRAPHS + 1) * D / 256 + 1;
    const int NB_ND = (N_NODES * D + 255) / 256;
    const int NB_W  = (D * D + 255) / 256;
    const int gemm_grid = (N_NODES + M_BLK - 1) / M_BLK;   // 1563 (padded buffers)

    // ---- setup: CSR, dinv, pool counts, x -> bf16 hi/lo ----
    k_init<<<NB_N, 256>>>();
    k_count_deg<<<NB_E, 256>>>(e_dst);
    k_finish_dinv<<<NB_N, 256>>>();
    k_scan1<<<N_SCANBLK, SCAN_B>>>();
    k_scan2<<<1, 32>>>();
    k_scan3<<<NB_N, 256>>>();
    k_fill<<<NB_E, 256>>>(e_src, e_dst);
    k_zero_pool<<<NB_G, 256>>>();
    k_count_batch<<<NB_N, 256>>>(batch);
    k_cvt_x<<<NB_ND, 256>>>(x);

    // ---- layer 0 ----
    k_cvt_w<<<NB_W, 256>>>(W0);
    k_gemm_tc<<<gemm_grid, 256>>>();
    k_gather<0><<<NB_NW, 256>>>(b0, nullptr);
    // ---- layer 1 ----
    k_cvt_w<<<NB_W, 256>>>(W1);
    k_gemm_tc<<<gemm_grid, 256>>>();
    k_gather<0><<<NB_NW, 256>>>(b1, nullptr);
    // ---- layer 2 (fused mean-pool) ----
    k_cvt_w<<<NB_W, 256>>>(W2);
    k_gemm_tc<<<gemm_grid, 256>>>();
    k_gather<1><<<NB_NW, 256>>>(b2, batch);

    // ---- classifier ----
    k_classify<<<N_GRAPHS, 128>>>(Wc, bc, out);
}

// round 10
// speedup vs baseline: 3.0423x; 1.0026x over previous
#include <cuda_runtime.h>
#include <cuda_bf16.h>
#include <mma.h>
using namespace nvcuda;

#define N_NODES   100000
#define N_EDGES   1600000
#define D         128
#define N_GRAPHS  512
#define N_CLASSES 10
#define SCAN_B    512
#define N_SCANBLK ((N_NODES + SCAN_B - 1) / SCAN_B)   // 196
#define M_BLK     64
#define KC        64
#define N_PAD     64

// -------- scratch: __device__ globals, referenced ONLY inside device code --------
__device__ float          g_h[(N_NODES + N_PAD) * D];   // h = x @ W (fp32)
__device__ __nv_bfloat16  g_xh[(N_NODES + N_PAD) * D];  // activation hi (bf16)
__device__ __nv_bfloat16  g_xl[(N_NODES + N_PAD) * D];  // activation lo (bf16 residual)
__device__ float g_dinv[N_NODES];
__device__ int   g_deg[N_NODES];
__device__ int   g_cnt[N_NODES];
__device__ int   g_rowex[N_NODES];
__device__ int   g_row[N_NODES + 1];
__device__ int   g_bsum[N_SCANBLK];
__device__ int   g_boff[N_SCANBLK];
__device__ int   g_csr_src[N_EDGES];
__device__ float g_csr_nrm[N_EDGES];
__device__ float g_sums[N_GRAPHS * D];
__device__ float g_cnts[N_GRAPHS];

// ----------------- setup (fused) -----------------
// zero: deg, cnt, sums, cnts  (grid covers N_NODES > N_GRAPHS*D)
__global__ __launch_bounds__(256) void k_init() {
    int i = blockIdx.x * blockDim.x + threadIdx.x;
    if (i < N_NODES) { g_deg[i] = 0; g_cnt[i] = 0; }
    if (i < N_GRAPHS * D) g_sums[i] = 0.f;
    if (i < N_GRAPHS) g_cnts[i] = 0.f;
}
__global__ __launch_bounds__(256) void k_count_deg(const int* __restrict__ dst) {
    int e = blockIdx.x * blockDim.x + threadIdx.x;
    if (e < N_EDGES) atomicAdd(&g_deg[dst[e]], 1);
}
// scan stage 1 + dinv computation (both read g_deg)
__global__ __launch_bounds__(SCAN_B) void k_scan1() {
    __shared__ int s[SCAN_B];
    int tid = threadIdx.x;
    int gid = blockIdx.x * SCAN_B + tid;
    int v = (gid < N_NODES) ? g_deg[gid] : 0;
    if (gid < N_NODES) g_dinv[gid] = rsqrtf((float)v + 1.0f);
    s[tid] = v;
    __syncthreads();
    #pragma unroll
    for (int off = 1; off < SCAN_B; off <<= 1) {
        int t = (tid >= off) ? s[tid - off] : 0;
        __syncthreads();
        s[tid] += t;
        __syncthreads();
    }
    if (gid < N_NODES) g_rowex[gid] = s[tid] - v;
    if (tid == SCAN_B - 1) g_bsum[blockIdx.x] = s[tid];
}
__global__ __launch_bounds__(32) void k_scan2() {
    if (threadIdx.x == 0) {
        int run = 0;
        for (int b = 0; b < N_SCANBLK; b++) { g_boff[b] = run; run += g_bsum[b]; }
        g_row[N_NODES] = run;
    }
}
// scan stage 3 + per-graph node counts (both node-indexed)
__global__ __launch_bounds__(256) void k_scan3(const int* __restrict__ batch) {
    int i = blockIdx.x * blockDim.x + threadIdx.x;
    if (i < N_NODES) {
        g_row[i] = g_rowex[i] + g_boff[i / SCAN_B];
        atomicAdd(&g_cnts[batch[i]], 1.0f);
    }
}
__global__ __launch_bounds__(256) void k_fill(const int* __restrict__ src,
                                              const int* __restrict__ dst) {
    int e = blockIdx.x * blockDim.x + threadIdx.x;
    if (e >= N_EDGES) return;
    int s = src[e], d = dst[e];
    int idx = g_row[d] + atomicAdd(&g_cnt[d], 1);
    g_csr_src[idx] = s;
    g_csr_nrm[idx] = g_dinv[s] * g_dinv[d];
}
// input x -> bf16 hi/lo
__global__ __launch_bounds__(256) void k_cvt_x(const float* __restrict__ x) {
    int i = blockIdx.x * blockDim.x + threadIdx.x;
    if (i >= N_NODES * D) return;
    float v = x[i];
    __nv_bfloat16 h = __float2bfloat16(v);
    g_xh[i] = h;
    g_xl[i] = __float2bfloat16(v - __bfloat162float(h));
}

// ----------------- tensor-core GEMM: h = X @ W via split-bf16 -----------------
// Xh@Wh + Xl@Wh + Xh@Wl, fp32 accum. W converted inline from fp32 during staging.
// Stage order reuses each Wh B-panel for the Xh and Xl products (4 B-loads, 6 A-loads).
__device__ __forceinline__ __nv_bfloat16 cvt_hi(float v) { return __float2bfloat16(v); }
__device__ __forceinline__ __nv_bfloat16 cvt_lo(float v) {
    __nv_bfloat16 h = __float2bfloat16(v);
    return __float2bfloat16(v - __bfloat162float(h));
}

__global__ __launch_bounds__(256) void k_gemm_tc(const float* __restrict__ Wf) {
    __shared__ __nv_bfloat16 As[M_BLK][KC + 8];   // 64x72
    __shared__ __nv_bfloat16 Bs[KC][D + 8];       // 64x136
    const int tid = threadIdx.x;
    const int wid = tid >> 5;
    const int wm = wid & 1;
    const int wn = wid >> 1;
    const int row0 = blockIdx.x * M_BLK;

    wmma::fragment<wmma::accumulator, 16, 16, 16, float> acc[2][2];
    #pragma unroll
    for (int i = 0; i < 2; i++)
        #pragma unroll
        for (int j = 0; j < 2; j++)
            wmma::fill_fragment(acc[i][j], 0.0f);

    // stage tables: A source (0=xh,1=xl), A col offset, B lo?(0=hi,1=lo), B row, load B?
    constexpr int ASRC[6] = {0, 1, 0, 1, 0, 0};
    constexpr int ACOL[6] = {0, 0, KC, KC, 0, KC};
    constexpr int BLO[6]  = {0, 0, 0, 0, 1, 1};
    constexpr int BROW[6] = {0, 0, KC, KC, 0, KC};
    constexpr int LDB[6]  = {1, 0, 1, 0, 1, 1};

    #pragma unroll
    for (int c = 0; c < 6; c++) {
        const __nv_bfloat16* Asrc = ASRC[c] ? g_xl : g_xh;

        __syncthreads();
        // A: 64x64 bf16 (8B vectors): 1024 groups / 256 thr = 4 each
        #pragma unroll
        for (int j = 0; j < 4; j++) {
            int idx = tid + j * 256;
            int r = idx >> 4, g = idx & 15;
            *(uint2*)&As[r][g * 4] =
                *(const uint2*)&Asrc[(size_t)(row0 + r) * D + ACOL[c] + g * 4];
        }
        if (LDB[c]) {
            // B: 64x128 from fp32 W with inline hi/lo conversion
            #pragma unroll
            for (int j = 0; j < 8; j++) {
                int idx = tid + j * 256;
                int r = idx >> 5, g = idx & 31;
                float4 wv = *(const float4*)&Wf[(size_t)(BROW[c] + r) * D + g * 4];
                __nv_bfloat162 p0, p1;
                if (BLO[c]) {
                    p0 = __nv_bfloat162{cvt_lo(wv.x), cvt_lo(wv.y)};
                    p1 = __nv_bfloat162{cvt_lo(wv.z), cvt_lo(wv.w)};
                } else {
                    p0 = __nv_bfloat162{cvt_hi(wv.x), cvt_hi(wv.y)};
                    p1 = __nv_bfloat162{cvt_hi(wv.z), cvt_hi(wv.w)};
                }
                *(__nv_bfloat162*)&Bs[r][g * 4]     = p0;
                *(__nv_bfloat162*)&Bs[r][g * 4 + 2] = p1;
            }
        }
        __syncthreads();

        #pragma unroll
        for (int kk = 0; kk < KC / 16; kk++) {
            wmma::fragment<wmma::matrix_a, 16, 16, 16, __nv_bfloat16, wmma::row_major> af[2];
            wmma::fragment<wmma::matrix_b, 16, 16, 16, __nv_bfloat16, wmma::row_major> bf[2];
            #pragma unroll
            for (int i = 0; i < 2; i++)
                wmma::load_matrix_sync(af[i], &As[wm * 32 + i * 16][kk * 16], KC + 8);
            #pragma unroll
            for (int j = 0; j < 2; j++)
                wmma::load_matrix_sync(bf[j], &Bs[kk * 16][wn * 32 + j * 16], D + 8);
            #pragma unroll
            for (int i = 0; i < 2; i++)
                #pragma unroll
                for (int j = 0; j < 2; j++)
                    wmma::mma_sync(acc[i][j], af[i], bf[j], acc[i][j]);
        }
    }

    #pragma unroll
    for (int i = 0; i < 2; i++)
        #pragma unroll
        for (int j = 0; j < 2; j++)
            wmma::store_matrix_sync(
                &g_h[(size_t)(row0 + wm * 32 + i * 16) * D + wn * 32 + j * 16],
                acc[i][j], D, wmma::mem_row_major);
}

// ----------------- fused aggregation (warp per node, 4-way MLP) -----------------
template <int LAST>
__global__ __launch_bounds__(256) void k_gather(const float* __restrict__ b,
                                                const int* __restrict__ batch) {
    int node = (blockIdx.x * blockDim.x + threadIdx.x) >> 5;
    int lane = threadIdx.x & 31;
    if (node >= N_NODES) return;

    const float4* h4 = (const float4*)g_h;
    int beg = g_row[node];
    int end = g_row[node + 1];

    float dv = g_dinv[node];
    float d2 = dv * dv;
    float4 acc = h4[(size_t)node * 32 + lane];
    acc.x *= d2; acc.y *= d2; acc.z *= d2; acc.w *= d2;

    int j = beg;
    int n4 = beg + ((end - beg) & ~3);
    for (; j < n4; j += 4) {
        int   s0 = __ldg(&g_csr_src[j]),     s1 = __ldg(&g_csr_src[j + 1]);
        int   s2 = __ldg(&g_csr_src[j + 2]), s3 = __ldg(&g_csr_src[j + 3]);
        float w0 = __ldg(&g_csr_nrm[j]),     w1 = __ldg(&g_csr_nrm[j + 1]);
        float w2 = __ldg(&g_csr_nrm[j + 2]), w3 = __ldg(&g_csr_nrm[j + 3]);
        float4 v0 = h4[(size_t)s0 * 32 + lane];
        float4 v1 = h4[(size_t)s1 * 32 + lane];
        float4 v2 = h4[(size_t)s2 * 32 + lane];
        float4 v3 = h4[(size_t)s3 * 32 + lane];
        acc.x += v0.x * w0; acc.y += v0.y * w0; acc.z += v0.z * w0; acc.w += v0.w * w0;
        acc.x += v1.x * w1; acc.y += v1.y * w1; acc.z += v1.z * w1; acc.w += v1.w * w1;
        acc.x += v2.x * w2; acc.y += v2.y * w2; acc.z += v2.z * w2; acc.w += v2.w * w2;
        acc.x += v3.x * w3; acc.y += v3.y * w3; acc.z += v3.z * w3; acc.w += v3.w * w3;
    }
    for (; j < end; j++) {
        int   s0 = __ldg(&g_csr_src[j]);
        float w0 = __ldg(&g_csr_nrm[j]);
        float4 v0 = h4[(size_t)s0 * 32 + lane];
        acc.x += v0.x * w0; acc.y += v0.y * w0; acc.z += v0.z * w0; acc.w += v0.w * w0;
    }

    float4 bb = ((const float4*)b)[lane];
    acc.x = fmaxf(acc.x + bb.x, 0.f);
    acc.y = fmaxf(acc.y + bb.y, 0.f);
    acc.z = fmaxf(acc.z + bb.z, 0.f);
    acc.w = fmaxf(acc.w + bb.w, 0.f);

    if (LAST) {
        int bg = __ldg(&batch[node]);
        float* sp = g_sums + (size_t)bg * D + lane * 4;
        atomicAdd(sp + 0, acc.x);
        atomicAdd(sp + 1, acc.y);
        atomicAdd(sp + 2, acc.z);
        atomicAdd(sp + 3, acc.w);
    } else {
        __nv_bfloat16 hx = __float2bfloat16(acc.x);
        __nv_bfloat16 hy = __float2bfloat16(acc.y);
        __nv_bfloat16 hz = __float2bfloat16(acc.z);
        __nv_bfloat16 hw = __float2bfloat16(acc.w);
        __nv_bfloat162* xh2 = (__nv_bfloat162*)g_xh;
        __nv_bfloat162* xl2 = (__nv_bfloat162*)g_xl;
        size_t base = (size_t)node * 64 + lane * 2;
        xh2[base + 0] = __nv_bfloat162{hx, hy};
        xh2[base + 1] = __nv_bfloat162{hz, hw};
        xl2[base + 0] = __nv_bfloat162{
            __float2bfloat16(acc.x - __bfloat162float(hx)),
            __float2bfloat16(acc.y - __bfloat162float(hy))};
        xl2[base + 1] = __nv_bfloat162{
            __float2bfloat16(acc.z - __bfloat162float(hz)),
            __float2bfloat16(acc.w - __bfloat162float(hw))};
    }
}

// ----------------- classifier -----------------
__global__ __launch_bounds__(128) void k_classify(const float* __restrict__ Wc,
                                                  const float* __restrict__ bc,
                                                  float* __restrict__ out) {
    __shared__ float s[N_CLASSES];
    int g = blockIdx.x;
    int tid = threadIdx.x;
    if (tid < N_CLASSES) s[tid] = 0.f;
    __syncthreads();
    float cnt = fmaxf(g_cnts[g], 1.0f);
    float p = g_sums[(size_t)g * D + tid] / cnt;
    #pragma unroll
    for (int c = 0; c < N_CLASSES; c++)
        atomicAdd(&s[c], p * Wc[tid * N_CLASSES + c]);
    __syncthreads();
    if (tid < N_CLASSES) out[g * N_CLASSES + tid] = s[tid] + bc[tid];
}

// ---------------------------------------------------------------
extern "C" void kernel_launch(void* const* d_in, const int* in_sizes, int n_in,
                              void* d_out, int out_size) {
    const float* x       = (const float*)d_in[0];
    const int*   e_src   = (const int*)d_in[1];
    const int*   e_dst   = (const int*)d_in[2];
    const int*   batch   = (const int*)d_in[3];
    const float* W0 = (const float*)d_in[4];  const float* b0 = (const float*)d_in[5];
    const float* W1 = (const float*)d_in[6];  const float* b1 = (const float*)d_in[7];
    const float* W2 = (const float*)d_in[8];  const float* b2 = (const float*)d_in[9];
    const float* Wc = (const float*)d_in[10]; const float* bc = (const float*)d_in[11];
    float* out = (float*)d_out;

    const int NB_N  = (N_NODES + 255) / 256;
    const int NB_E  = (N_EDGES + 255) / 256;
    const int NB_NW = (N_NODES * 32 + 255) / 256;
    const int NB_ND = (N_NODES * D + 255) / 256;
    const int gemm_grid = (N_NODES + M_BLK - 1) / M_BLK;   // 1563

    // ---- setup (7 launches): CSR + dinv + pool counts + x conversion ----
    k_init<<<NB_N, 256>>>();
    k_count_deg<<<NB_E, 256>>>(e_dst);
    k_scan1<<<N_SCANBLK, SCAN_B>>>();
    k_scan2<<<1, 32>>>();
    k_scan3<<<NB_N, 256>>>(batch);
    k_fill<<<NB_E, 256>>>(e_src, e_dst);
    k_cvt_x<<<NB_ND, 256>>>(x);

    // ---- layer 0 ----
    k_gemm_tc<<<gemm_grid, 256>>>(W0);
    k_gather<0><<<NB_NW, 256>>>(b0, nullptr);
    // ---- layer 1 ----
    k_gemm_tc<<<gemm_grid, 256>>>(W1);
    k_gather<0><<<NB_NW, 256>>>(b1, nullptr);
    // ---- layer 2 (fused mean-pool) ----
    k_gemm_tc<<<gemm_grid, 256>>>(W2);
    k_gather<1><<<NB_NW, 256>>>(b2, batch);

    // ---- classifier ----
    k_classify<<<N_GRAPHS, 128>>>(Wc, bc, out);
}

// round 11
// speedup vs baseline: 3.1080x; 1.0216x over previous
#include <cuda_runtime.h>
#include <cuda_bf16.h>
#include <mma.h>
using namespace nvcuda;

#define N_NODES   100000
#define N_EDGES   1600000
#define D         128
#define N_GRAPHS  512
#define N_CLASSES 10
#define SCAN_B    512
#define N_SCANBLK ((N_NODES + SCAN_B - 1) / SCAN_B)   // 196
#define M_BLK     64
#define KC        64
#define N_PAD     64

// -------- scratch: __device__ globals, referenced ONLY inside device code --------
__device__ float          g_h[(N_NODES + N_PAD) * D];   // h = x @ W (fp32)
__device__ __nv_bfloat16  g_xh[(N_NODES + N_PAD) * D];  // activation hi (bf16)
__device__ __nv_bfloat16  g_xl[(N_NODES + N_PAD) * D];  // activation lo (bf16 residual)
__device__ float g_dinv[N_NODES];
__device__ int   g_deg[N_NODES];
__device__ int   g_cnt[N_NODES];
__device__ int   g_rowex[N_NODES];
__device__ int   g_row[N_NODES + 1];
__device__ int   g_bsum[N_SCANBLK];
__device__ int   g_boff[N_SCANBLK];
__device__ int   g_csr_src[N_EDGES];
__device__ float g_csr_nrm[N_EDGES];
__device__ float g_sums[N_GRAPHS * D];
__device__ float g_cnts[N_GRAPHS];

// ----------------- setup (fused) -----------------
__global__ __launch_bounds__(256) void k_init() {
    int i = blockIdx.x * blockDim.x + threadIdx.x;
    if (i < N_NODES) { g_deg[i] = 0; g_cnt[i] = 0; }
    if (i < N_GRAPHS * D) g_sums[i] = 0.f;
    if (i < N_GRAPHS) g_cnts[i] = 0.f;
}
__global__ __launch_bounds__(256) void k_count_deg(const int* __restrict__ dst) {
    int e = blockIdx.x * blockDim.x + threadIdx.x;
    if (e < N_EDGES) atomicAdd(&g_deg[dst[e]], 1);
}
// scan stage 1 + dinv computation (both read g_deg)
__global__ __launch_bounds__(SCAN_B) void k_scan1() {
    __shared__ int s[SCAN_B];
    int tid = threadIdx.x;
    int gid = blockIdx.x * SCAN_B + tid;
    int v = (gid < N_NODES) ? g_deg[gid] : 0;
    if (gid < N_NODES) g_dinv[gid] = rsqrtf((float)v + 1.0f);
    s[tid] = v;
    __syncthreads();
    #pragma unroll
    for (int off = 1; off < SCAN_B; off <<= 1) {
        int t = (tid >= off) ? s[tid - off] : 0;
        __syncthreads();
        s[tid] += t;
        __syncthreads();
    }
    if (gid < N_NODES) g_rowex[gid] = s[tid] - v;
    if (tid == SCAN_B - 1) g_bsum[blockIdx.x] = s[tid];
}
// parallel scan of the 196 block sums (one 256-thread block, Hillis-Steele)
__global__ __launch_bounds__(256) void k_scan2() {
    __shared__ int s[256];
    int tid = threadIdx.x;
    int v = (tid < N_SCANBLK) ? g_bsum[tid] : 0;
    s[tid] = v;
    __syncthreads();
    #pragma unroll
    for (int off = 1; off < 256; off <<= 1) {
        int t = (tid >= off) ? s[tid - off] : 0;
        __syncthreads();
        s[tid] += t;
        __syncthreads();
    }
    if (tid < N_SCANBLK) g_boff[tid] = s[tid] - v;          // exclusive
    if (tid == 255) g_row[N_NODES] = s[255];                // total == N_EDGES
}
// scan stage 3 + per-graph node counts (both node-indexed)
__global__ __launch_bounds__(256) void k_scan3(const int* __restrict__ batch) {
    int i = blockIdx.x * blockDim.x + threadIdx.x;
    if (i < N_NODES) {
        g_row[i] = g_rowex[i] + g_boff[i / SCAN_B];
        atomicAdd(&g_cnts[batch[i]], 1.0f);
    }
}
__global__ __launch_bounds__(256) void k_fill(const int* __restrict__ src,
                                              const int* __restrict__ dst) {
    int e = blockIdx.x * blockDim.x + threadIdx.x;
    if (e >= N_EDGES) return;
    int s = src[e], d = dst[e];
    int idx = g_row[d] + atomicAdd(&g_cnt[d], 1);
    g_csr_src[idx] = s;
    g_csr_nrm[idx] = g_dinv[s] * g_dinv[d];
}
// input x -> bf16 hi/lo
__global__ __launch_bounds__(256) void k_cvt_x(const float* __restrict__ x) {
    int i = blockIdx.x * blockDim.x + threadIdx.x;
    if (i >= N_NODES * D) return;
    float v = x[i];
    __nv_bfloat16 h = __float2bfloat16(v);
    g_xh[i] = h;
    g_xl[i] = __float2bfloat16(v - __bfloat162float(h));
}

// ----------------- tensor-core GEMM: h = X @ W via split-bf16 -----------------
__device__ __forceinline__ __nv_bfloat16 cvt_hi(float v) { return __float2bfloat16(v); }
__device__ __forceinline__ __nv_bfloat16 cvt_lo(float v) {
    __nv_bfloat16 h = __float2bfloat16(v);
    return __float2bfloat16(v - __bfloat162float(h));
}

__global__ __launch_bounds__(256) void k_gemm_tc(const float* __restrict__ Wf) {
    __shared__ __nv_bfloat16 As[M_BLK][KC + 8];   // 64x72
    __shared__ __nv_bfloat16 Bs[KC][D + 8];       // 64x136
    const int tid = threadIdx.x;
    const int wid = tid >> 5;
    const int wm = wid & 1;
    const int wn = wid >> 1;
    const int row0 = blockIdx.x * M_BLK;

    wmma::fragment<wmma::accumulator, 16, 16, 16, float> acc[2][2];
    #pragma unroll
    for (int i = 0; i < 2; i++)
        #pragma unroll
        for (int j = 0; j < 2; j++)
            wmma::fill_fragment(acc[i][j], 0.0f);

    constexpr int ASRC[6] = {0, 1, 0, 1, 0, 0};
    constexpr int ACOL[6] = {0, 0, KC, KC, 0, KC};
    constexpr int BLO[6]  = {0, 0, 0, 0, 1, 1};
    constexpr int BROW[6] = {0, 0, KC, KC, 0, KC};
    constexpr int LDB[6]  = {1, 0, 1, 0, 1, 1};

    #pragma unroll
    for (int c = 0; c < 6; c++) {
        const __nv_bfloat16* Asrc = ASRC[c] ? g_xl : g_xh;

        __syncthreads();
        #pragma unroll
        for (int j = 0; j < 4; j++) {
            int idx = tid + j * 256;
            int r = idx >> 4, g = idx & 15;
            *(uint2*)&As[r][g * 4] =
                *(const uint2*)&Asrc[(size_t)(row0 + r) * D + ACOL[c] + g * 4];
        }
        if (LDB[c]) {
            #pragma unroll
            for (int j = 0; j < 8; j++) {
                int idx = tid + j * 256;
                int r = idx >> 5, g = idx & 31;
                float4 wv = *(const float4*)&Wf[(size_t)(BROW[c] + r) * D + g * 4];
                __nv_bfloat162 p0, p1;
                if (BLO[c]) {
                    p0 = __nv_bfloat162{cvt_lo(wv.x), cvt_lo(wv.y)};
                    p1 = __nv_bfloat162{cvt_lo(wv.z), cvt_lo(wv.w)};
                } else {
                    p0 = __nv_bfloat162{cvt_hi(wv.x), cvt_hi(wv.y)};
                    p1 = __nv_bfloat162{cvt_hi(wv.z), cvt_hi(wv.w)};
                }
                *(__nv_bfloat162*)&Bs[r][g * 4]     = p0;
                *(__nv_bfloat162*)&Bs[r][g * 4 + 2] = p1;
            }
        }
        __syncthreads();

        #pragma unroll
        for (int kk = 0; kk < KC / 16; kk++) {
            wmma::fragment<wmma::matrix_a, 16, 16, 16, __nv_bfloat16, wmma::row_major> af[2];
            wmma::fragment<wmma::matrix_b, 16, 16, 16, __nv_bfloat16, wmma::row_major> bf[2];
            #pragma unroll
            for (int i = 0; i < 2; i++)
                wmma::load_matrix_sync(af[i], &As[wm * 32 + i * 16][kk * 16], KC + 8);
            #pragma unroll
            for (int j = 0; j < 2; j++)
                wmma::load_matrix_sync(bf[j], &Bs[kk * 16][wn * 32 + j * 16], D + 8);
            #pragma unroll
            for (int i = 0; i < 2; i++)
                #pragma unroll
                for (int j = 0; j < 2; j++)
                    wmma::mma_sync(acc[i][j], af[i], bf[j], acc[i][j]);
        }
    }

    #pragma unroll
    for (int i = 0; i < 2; i++)
        #pragma unroll
        for (int j = 0; j < 2; j++)
            wmma::store_matrix_sync(
                &g_h[(size_t)(row0 + wm * 32 + i * 16) * D + wn * 32 + j * 16],
                acc[i][j], D, wmma::mem_row_major);
}

// ----------------- fused aggregation (warp per node) -----------------
template <int LAST>
__global__ __launch_bounds__(256) void k_gather(const float* __restrict__ b,
                                                const int* __restrict__ batch) {
    int node = (blockIdx.x * blockDim.x + threadIdx.x) >> 5;
    int lane = threadIdx.x & 31;
    if (node >= N_NODES) return;

    const float4* h4 = (const float4*)g_h;
    int beg = g_row[node];
    int end = g_row[node + 1];

    float dv = g_dinv[node];
    float d2 = dv * dv;
    float4 acc = h4[(size_t)node * 32 + lane];
    acc.x *= d2; acc.y *= d2; acc.z *= d2; acc.w *= d2;

    int j = beg;
    int n4 = beg + ((end - beg) & ~3);
    for (; j < n4; j += 4) {
        int   s0 = __ldg(&g_csr_src[j]),     s1 = __ldg(&g_csr_src[j + 1]);
        int   s2 = __ldg(&g_csr_src[j + 2]), s3 = __ldg(&g_csr_src[j + 3]);
        float w0 = __ldg(&g_csr_nrm[j]),     w1 = __ldg(&g_csr_nrm[j + 1]);
        float w2 = __ldg(&g_csr_nrm[j + 2]), w3 = __ldg(&g_csr_nrm[j + 3]);
        float4 v0 = h4[(size_t)s0 * 32 + lane];
        float4 v1 = h4[(size_t)s1 * 32 + lane];
        float4 v2 = h4[(size_t)s2 * 32 + lane];
        float4 v3 = h4[(size_t)s3 * 32 + lane];
        acc.x += v0.x * w0; acc.y += v0.y * w0; acc.z += v0.z * w0; acc.w += v0.w * w0;
        acc.x += v1.x * w1; acc.y += v1.y * w1; acc.z += v1.z * w1; acc.w += v1.w * w1;
        acc.x += v2.x * w2; acc.y += v2.y * w2; acc.z += v2.z * w2; acc.w += v2.w * w2;
        acc.x += v3.x * w3; acc.y += v3.y * w3; acc.z += v3.z * w3; acc.w += v3.w * w3;
    }
    for (; j < end; j++) {
        int   s0 = __ldg(&g_csr_src[j]);
        float w0 = __ldg(&g_csr_nrm[j]);
        float4 v0 = h4[(size_t)s0 * 32 + lane];
        acc.x += v0.x * w0; acc.y += v0.y * w0; acc.z += v0.z * w0; acc.w += v0.w * w0;
    }

    float4 bb = ((const float4*)b)[lane];
    acc.x = fmaxf(acc.x + bb.x, 0.f);
    acc.y = fmaxf(acc.y + bb.y, 0.f);
    acc.z = fmaxf(acc.z + bb.z, 0.f);
    acc.w = fmaxf(acc.w + bb.w, 0.f);

    if (LAST) {
        int bg = __ldg(&batch[node]);
        float* sp = g_sums + (size_t)bg * D + lane * 4;
        atomicAdd(sp + 0, acc.x);
        atomicAdd(sp + 1, acc.y);
        atomicAdd(sp + 2, acc.z);
        atomicAdd(sp + 3, acc.w);
    } else {
        __nv_bfloat16 hx = __float2bfloat16(acc.x);
        __nv_bfloat16 hy = __float2bfloat16(acc.y);
        __nv_bfloat16 hz = __float2bfloat16(acc.z);
        __nv_bfloat16 hw = __float2bfloat16(acc.w);
        __nv_bfloat162* xh2 = (__nv_bfloat162*)g_xh;
        __nv_bfloat162* xl2 = (__nv_bfloat162*)g_xl;
        size_t base = (size_t)node * 64 + lane * 2;
        xh2[base + 0] = __nv_bfloat162{hx, hy};
        xh2[base + 1] = __nv_bfloat162{hz, hw};
        xl2[base + 0] = __nv_bfloat162{
            __float2bfloat16(acc.x - __bfloat162float(hx)),
            __float2bfloat16(acc.y - __bfloat162float(hy))};
        xl2[base + 1] = __nv_bfloat162{
            __float2bfloat16(acc.z - __bfloat162float(hz)),
            __float2bfloat16(acc.w - __bfloat162float(hw))};
    }
}

// ----------------- classifier -----------------
__global__ __launch_bounds__(128) void k_classify(const float* __restrict__ Wc,
                                                  const float* __restrict__ bc,
                                                  float* __restrict__ out) {
    __shared__ float s[N_CLASSES];
    int g = blockIdx.x;
    int tid = threadIdx.x;
    if (tid < N_CLASSES) s[tid] = 0.f;
    __syncthreads();
    float cnt = fmaxf(g_cnts[g], 1.0f);
    float p = g_sums[(size_t)g * D + tid] / cnt;
    #pragma unroll
    for (int c = 0; c < N_CLASSES; c++)
        atomicAdd(&s[c], p * Wc[tid * N_CLASSES + c]);
    __syncthreads();
    if (tid < N_CLASSES) out[g * N_CLASSES + tid] = s[tid] + bc[tid];
}

// ---------------------------------------------------------------
extern "C" void kernel_launch(void* const* d_in, const int* in_sizes, int n_in,
                              void* d_out, int out_size) {
    const float* x       = (const float*)d_in[0];
    const int*   e_src   = (const int*)d_in[1];
    const int*   e_dst   = (const int*)d_in[2];
    const int*   batch   = (const int*)d_in[3];
    const float* W0 = (const float*)d_in[4];  const float* b0 = (const float*)d_in[5];
    const float* W1 = (const float*)d_in[6];  const float* b1 = (const float*)d_in[7];
    const float* W2 = (const float*)d_in[8];  const float* b2 = (const float*)d_in[9];
    const float* Wc = (const float*)d_in[10]; const float* bc = (const float*)d_in[11];
    float* out = (float*)d_out;

    const int NB_N  = (N_NODES + 255) / 256;
    const int NB_E  = (N_EDGES + 255) / 256;
    const int NB_NW = (N_NODES * 32 + 255) / 256;
    const int NB_ND = (N_NODES * D + 255) / 256;
    const int gemm_grid = (N_NODES + M_BLK - 1) / M_BLK;   // 1563

    // One-time creation of side stream + fork/join events (host objects only;
    // no device memory). First call happens outside graph capture.
    static cudaStream_t s2 = nullptr;
    static cudaEvent_t evFork = nullptr, evJoin = nullptr;
    if (s2 == nullptr) {
        cudaStreamCreate(&s2);
        cudaEventCreateWithFlags(&evFork, cudaEventDisableTiming);
        cudaEventCreateWithFlags(&evJoin, cudaEventDisableTiming);
    }

    // ---- fork: CSR build on s2  ||  cvt_x + layer-0 GEMM on main stream ----
    cudaEventRecord(evFork, 0);
    cudaStreamWaitEvent(s2, evFork, 0);

    // side stream: CSR + dinv + pool counts
    k_init<<<NB_N, 256, 0, s2>>>();
    k_count_deg<<<NB_E, 256, 0, s2>>>(e_dst);
    k_scan1<<<N_SCANBLK, SCAN_B, 0, s2>>>();
    k_scan2<<<1, 256, 0, s2>>>();
    k_scan3<<<NB_N, 256, 0, s2>>>(batch);
    k_fill<<<NB_E, 256, 0, s2>>>(e_src, e_dst);

    // main stream: input conversion + layer-0 GEMM (independent of CSR)
    k_cvt_x<<<NB_ND, 256>>>(x);
    k_gemm_tc<<<gemm_grid, 256>>>(W0);

    // join
    cudaEventRecord(evJoin, s2);
    cudaStreamWaitEvent(0, evJoin, 0);

    // ---- layer 0 aggregation ----
    k_gather<0><<<NB_NW, 256>>>(b0, nullptr);
    // ---- layer 1 ----
    k_gemm_tc<<<gemm_grid, 256>>>(W1);
    k_gather<0><<<NB_NW, 256>>>(b1, nullptr);
    // ---- layer 2 (fused mean-pool) ----
    k_gemm_tc<<<gemm_grid, 256>>>(W2);
    k_gather<1><<<NB_NW, 256>>>(b2, batch);

    // ---- classifier ----
    k_classify<<<N_GRAPHS, 128>>>(Wc, bc, out);
}

// round 13
// speedup vs baseline: 3.1427x; 1.0112x over previous
#include <cuda_runtime.h>
#include <cuda_bf16.h>
#include <mma.h>
using namespace nvcuda;

#define N_NODES   100000
#define N_EDGES   1600000
#define D         128
#define N_GRAPHS  512
#define N_CLASSES 10
#define SCAN_B    512
#define N_SCANBLK ((N_NODES + SCAN_B - 1) / SCAN_B)   // 196
#define M_BLK     64
#define KC        64
#define N_PAD     64

// -------- scratch: __device__ globals, referenced ONLY inside device code --------
__device__ __nv_bfloat16  g_hh[(N_NODES + N_PAD) * D];  // h hi (bf16)
__device__ __nv_bfloat16  g_hl[(N_NODES + N_PAD) * D];  // h lo (bf16 residual)
__device__ __nv_bfloat16  g_xh[(N_NODES + N_PAD) * D];  // activation hi
__device__ __nv_bfloat16  g_xl[(N_NODES + N_PAD) * D];  // activation lo
__device__ float g_dinv[N_NODES];
__device__ int   g_deg[N_NODES];
__device__ int   g_cnt[N_NODES];
__device__ int   g_rowex[N_NODES];
__device__ int   g_row[N_NODES + 1];
__device__ int   g_bsum[N_SCANBLK];
__device__ int   g_boff[N_SCANBLK];
__device__ int   g_csr_src[N_EDGES];
__device__ float g_csr_nrm[N_EDGES];
__device__ float g_sums[N_GRAPHS * D];
__device__ float g_cnts[N_GRAPHS];

// ----------------- setup (fused) -----------------
__global__ __launch_bounds__(256) void k_init() {
    int i = blockIdx.x * blockDim.x + threadIdx.x;
    if (i < N_NODES) { g_deg[i] = 0; g_cnt[i] = 0; }
    if (i < N_GRAPHS * D) g_sums[i] = 0.f;
    if (i < N_GRAPHS) g_cnts[i] = 0.f;
}
__global__ __launch_bounds__(256) void k_count_deg(const int* __restrict__ dst) {
    int e = blockIdx.x * blockDim.x + threadIdx.x;
    if (e < N_EDGES) atomicAdd(&g_deg[dst[e]], 1);
}
__global__ __launch_bounds__(SCAN_B) void k_scan1() {
    __shared__ int s[SCAN_B];
    int tid = threadIdx.x;
    int gid = blockIdx.x * SCAN_B + tid;
    int v = (gid < N_NODES) ? g_deg[gid] : 0;
    if (gid < N_NODES) g_dinv[gid] = rsqrtf((float)v + 1.0f);
    s[tid] = v;
    __syncthreads();
    #pragma unroll
    for (int off = 1; off < SCAN_B; off <<= 1) {
        int t = (tid >= off) ? s[tid - off] : 0;
        __syncthreads();
        s[tid] += t;
        __syncthreads();
    }
    if (gid < N_NODES) g_rowex[gid] = s[tid] - v;
    if (tid == SCAN_B - 1) g_bsum[blockIdx.x] = s[tid];
}
__global__ __launch_bounds__(256) void k_scan2() {
    __shared__ int s[256];
    int tid = threadIdx.x;
    int v = (tid < N_SCANBLK) ? g_bsum[tid] : 0;
    s[tid] = v;
    __syncthreads();
    #pragma unroll
    for (int off = 1; off < 256; off <<= 1) {
        int t = (tid >= off) ? s[tid - off] : 0;
        __syncthreads();
        s[tid] += t;
        __syncthreads();
    }
    if (tid < N_SCANBLK) g_boff[tid] = s[tid] - v;
    if (tid == 255) g_row[N_NODES] = s[255];
}
__global__ __launch_bounds__(256) void k_scan3(const int* __restrict__ batch) {
    int i = blockIdx.x * blockDim.x + threadIdx.x;
    if (i < N_NODES) {
        g_row[i] = g_rowex[i] + g_boff[i / SCAN_B];
        atomicAdd(&g_cnts[batch[i]], 1.0f);
    }
}
__global__ __launch_bounds__(256) void k_fill(const int* __restrict__ src,
                                              const int* __restrict__ dst) {
    int e = blockIdx.x * blockDim.x + threadIdx.x;
    if (e >= N_EDGES) return;
    int s = src[e], d = dst[e];
    int idx = g_row[d] + atomicAdd(&g_cnt[d], 1);
    g_csr_src[idx] = s;
    g_csr_nrm[idx] = g_dinv[s] * g_dinv[d];
}
__global__ __launch_bounds__(256) void k_cvt_x(const float* __restrict__ x) {
    int i = blockIdx.x * blockDim.x + threadIdx.x;
    if (i >= N_NODES * D) return;
    float v = x[i];
    __nv_bfloat16 h = __float2bfloat16(v);
    g_xh[i] = h;
    g_xl[i] = __float2bfloat16(v - __bfloat162float(h));
}

// ----------------- helpers -----------------
__device__ __forceinline__ __nv_bfloat16 cvt_hi(float v) { return __float2bfloat16(v); }
__device__ __forceinline__ __nv_bfloat16 cvt_lo(float v) {
    __nv_bfloat16 h = __float2bfloat16(v);
    return __float2bfloat16(v - __bfloat162float(h));
}
__device__ __forceinline__ float4 bf4_to_f4(uint2 u) {
    __nv_bfloat162 a = *(__nv_bfloat162*)&u.x;
    __nv_bfloat162 b = *(__nv_bfloat162*)&u.y;
    float2 fa = __bfloat1622float2(a);
    float2 fb = __bfloat1622float2(b);
    return make_float4(fa.x, fa.y, fb.x, fb.y);
}

// ----------------- tensor-core GEMM: h = X @ W, split-bf16, bf16 hi/lo output --------
// Smem buffer aliased: mainloop stages As/Bs (26.6KB); epilogue stages C fp32 (33.8KB).
#define SMEM_BYTES 33792
__global__ __launch_bounds__(256) void k_gemm_tc(const float* __restrict__ Wf) {
    __shared__ __align__(16) char smem_raw[SMEM_BYTES];
    __nv_bfloat16* As = (__nv_bfloat16*)smem_raw;            // [64][KC+8]
    __nv_bfloat16* Bs = (__nv_bfloat16*)(smem_raw + M_BLK * (KC + 8) * 2);  // [64][D+8]
    float* Cs = (float*)smem_raw;                             // [64][D+4]
    const int tid = threadIdx.x;
    const int wid = tid >> 5;
    const int wm = wid & 1;
    const int wn = wid >> 1;
    const int row0 = blockIdx.x * M_BLK;

    wmma::fragment<wmma::accumulator, 16, 16, 16, float> acc[2][2];
    #pragma unroll
    for (int i = 0; i < 2; i++)
        #pragma unroll
        for (int j = 0; j < 2; j++)
            wmma::fill_fragment(acc[i][j], 0.0f);

    constexpr int ASRC[6] = {0, 1, 0, 1, 0, 0};
    constexpr int ACOL[6] = {0, 0, KC, KC, 0, KC};
    constexpr int BLO[6]  = {0, 0, 0, 0, 1, 1};
    constexpr int BROW[6] = {0, 0, KC, KC, 0, KC};
    constexpr int LDB[6]  = {1, 0, 1, 0, 1, 1};

    #pragma unroll
    for (int c = 0; c < 6; c++) {
        const __nv_bfloat16* Asrc = ASRC[c] ? g_xl : g_xh;

        __syncthreads();
        #pragma unroll
        for (int j = 0; j < 4; j++) {
            int idx = tid + j * 256;
            int r = idx >> 4, g = idx & 15;
            *(uint2*)&As[r * (KC + 8) + g * 4] =
                *(const uint2*)&Asrc[(size_t)(row0 + r) * D + ACOL[c] + g * 4];
        }
        if (LDB[c]) {
            #pragma unroll
            for (int j = 0; j < 8; j++) {
                int idx = tid + j * 256;
                int r = idx >> 5, g = idx & 31;
                float4 wv = *(const float4*)&Wf[(size_t)(BROW[c] + r) * D + g * 4];
                __nv_bfloat162 p0, p1;
                if (BLO[c]) {
                    p0 = __nv_bfloat162{cvt_lo(wv.x), cvt_lo(wv.y)};
                    p1 = __nv_bfloat162{cvt_lo(wv.z), cvt_lo(wv.w)};
                } else {
                    p0 = __nv_bfloat162{cvt_hi(wv.x), cvt_hi(wv.y)};
                    p1 = __nv_bfloat162{cvt_hi(wv.z), cvt_hi(wv.w)};
                }
                *(__nv_bfloat162*)&Bs[r * (D + 8) + g * 4]     = p0;
                *(__nv_bfloat162*)&Bs[r * (D + 8) + g * 4 + 2] = p1;
            }
        }
        __syncthreads();

        #pragma unroll
        for (int kk = 0; kk < KC / 16; kk++) {
            wmma::fragment<wmma::matrix_a, 16, 16, 16, __nv_bfloat16, wmma::row_major> af[2];
            wmma::fragment<wmma::matrix_b, 16, 16, 16, __nv_bfloat16, wmma::row_major> bf[2];
            #pragma unroll
            for (int i = 0; i < 2; i++)
                wmma::load_matrix_sync(af[i], &As[(wm * 32 + i * 16) * (KC + 8) + kk * 16], KC + 8);
            #pragma unroll
            for (int j = 0; j < 2; j++)
                wmma::load_matrix_sync(bf[j], &Bs[(kk * 16) * (D + 8) + wn * 32 + j * 16], D + 8);
            #pragma unroll
            for (int i = 0; i < 2; i++)
                #pragma unroll
                for (int j = 0; j < 2; j++)
                    wmma::mma_sync(acc[i][j], af[i], bf[j], acc[i][j]);
        }
    }

    // ---- epilogue: fp32 accum -> smem -> packed bf16 hi/lo global ----
    __syncthreads();      // all As/Bs reads complete before aliasing as Cs
    #pragma unroll
    for (int i = 0; i < 2; i++)
        #pragma unroll
        for (int j = 0; j < 2; j++)
            wmma::store_matrix_sync(&Cs[(wm * 32 + i * 16) * (D + 4) + wn * 32 + j * 16],
                                    acc[i][j], D + 4, wmma::mem_row_major);
    __syncthreads();
    #pragma unroll
    for (int it = 0; it < 8; it++) {
        int idx = tid + it * 256;      // 0..2047 groups of 4 elems
        int r = idx >> 5, g = idx & 31;
        float4 v = *(const float4*)&Cs[r * (D + 4) + g * 4];
        __nv_bfloat16 hx = cvt_hi(v.x), hy = cvt_hi(v.y), hz = cvt_hi(v.z), hw = cvt_hi(v.w);
        __nv_bfloat162 ph0{hx, hy}, ph1{hz, hw};
        __nv_bfloat162 pl0{cvt_lo(v.x), cvt_lo(v.y)}, pl1{cvt_lo(v.z), cvt_lo(v.w)};
        uint2 uh, ul;
        uh.x = *(unsigned*)&ph0; uh.y = *(unsigned*)&ph1;
        ul.x = *(unsigned*)&pl0; ul.y = *(unsigned*)&pl1;
        *(uint2*)&g_hh[(size_t)(row0 + r) * D + g * 4] = uh;
        *(uint2*)&g_hl[(size_t)(row0 + r) * D + g * 4] = ul;
    }
}

// ----------------- fused aggregation (warp per node, bf16 neighbor gather) -----------------
// acc = dinv^2*(hi+lo)[n] + sum nrm * hi[src]  (neighbors hi-only: half traffic)
template <int LAST>
__global__ __launch_bounds__(256) void k_gather(const float* __restrict__ b,
                                                const int* __restrict__ batch) {
    int node = (blockIdx.x * blockDim.x + threadIdx.x) >> 5;
    int lane = threadIdx.x & 31;
    if (node >= N_NODES) return;

    const uint2* hh = (const uint2*)g_hh;    // 4 bf16 per uint2; 32 per row
    const uint2* hl = (const uint2*)g_hl;
    int beg = g_row[node];
    int end = g_row[node + 1];

    float dv = g_dinv[node];
    float d2 = dv * dv;
    float4 vh = bf4_to_f4(hh[(size_t)node * 32 + lane]);
    float4 vl = bf4_to_f4(hl[(size_t)node * 32 + lane]);
    float4 acc = make_float4(d2 * (vh.x + vl.x), d2 * (vh.y + vl.y),
                             d2 * (vh.z + vl.z), d2 * (vh.w + vl.w));

    int j = beg;
    int n4 = beg + ((end - beg) & ~3);
    for (; j < n4; j += 4) {
        int   s0 = __ldg(&g_csr_src[j]),     s1 = __ldg(&g_csr_src[j + 1]);
        int   s2 = __ldg(&g_csr_src[j + 2]), s3 = __ldg(&g_csr_src[j + 3]);
        float w0 = __ldg(&g_csr_nrm[j]),     w1 = __ldg(&g_csr_nrm[j + 1]);
        float w2 = __ldg(&g_csr_nrm[j + 2]), w3 = __ldg(&g_csr_nrm[j + 3]);
        float4 v0 = bf4_to_f4(hh[(size_t)s0 * 32 + lane]);
        float4 v1 = bf4_to_f4(hh[(size_t)s1 * 32 + lane]);
        float4 v2 = bf4_to_f4(hh[(size_t)s2 * 32 + lane]);
        float4 v3 = bf4_to_f4(hh[(size_t)s3 * 32 + lane]);
        acc.x += v0.x * w0; acc.y += v0.y * w0; acc.z += v0.z * w0; acc.w += v0.w * w0;
        acc.x += v1.x * w1; acc.y += v1.y * w1; acc.z += v1.z * w1; acc.w += v1.w * w1;
        acc.x += v2.x * w2; acc.y += v2.y * w2; acc.z += v2.z * w2; acc.w += v2.w * w2;
        acc.x += v3.x * w3; acc.y += v3.y * w3; acc.z += v3.z * w3; acc.w += v3.w * w3;
    }
    for (; j < end; j++) {
        int   s0 = __ldg(&g_csr_src[j]);
        float w0 = __ldg(&g_csr_nrm[j]);
        float4 v0 = bf4_to_f4(hh[(size_t)s0 * 32 + lane]);
        acc.x += v0.x * w0; acc.y += v0.y * w0; acc.z += v0.z * w0; acc.w += v0.w * w0;
    }

    float4 bb = ((const float4*)b)[lane];
    acc.x = fmaxf(acc.x + bb.x, 0.f);
    acc.y = fmaxf(acc.y + bb.y, 0.f);
    acc.z = fmaxf(acc.z + bb.z, 0.f);
    acc.w = fmaxf(acc.w + bb.w, 0.f);

    if (LAST) {
        int bg = __ldg(&batch[node]);
        float* sp = g_sums + (size_t)bg * D + lane * 4;
        atomicAdd(sp + 0, acc.x);
        atomicAdd(sp + 1, acc.y);
        atomicAdd(sp + 2, acc.z);
        atomicAdd(sp + 3, acc.w);
    } else {
        __nv_bfloat16 hx = cvt_hi(acc.x), hy = cvt_hi(acc.y);
        __nv_bfloat16 hz = cvt_hi(acc.z), hw = cvt_hi(acc.w);
        __nv_bfloat162* xh2 = (__nv_bfloat162*)g_xh;
        __nv_bfloat162* xl2 = (__nv_bfloat162*)g_xl;
        size_t base = (size_t)node * 64 + lane * 2;
        xh2[base + 0] = __nv_bfloat162{hx, hy};
        xh2[base + 1] = __nv_bfloat162{hz, hw};
        xl2[base + 0] = __nv_bfloat162{
            __float2bfloat16(acc.x - __bfloat162float(hx)),
            __float2bfloat16(acc.y - __bfloat162float(hy))};
        xl2[base + 1] = __nv_bfloat162{
            __float2bfloat16(acc.z - __bfloat162float(hz)),
            __float2bfloat16(acc.w - __bfloat162float(hw))};
    }
}

// ----------------- classifier -----------------
__global__ __launch_bounds__(128) void k_classify(const float* __restrict__ Wc,
                                                  const float* __restrict__ bc,
                                                  float* __restrict__ out) {
    __shared__ float s[N_CLASSES];
    int g = blockIdx.x;
    int tid = threadIdx.x;
    if (tid < N_CLASSES) s[tid] = 0.f;
    __syncthreads();
    float cnt = fmaxf(g_cnts[g], 1.0f);
    float p = g_sums[(size_t)g * D + tid] / cnt;
    #pragma unroll
    for (int c = 0; c < N_CLASSES; c++)
        atomicAdd(&s[c], p * Wc[tid * N_CLASSES + c]);
    __syncthreads();
    if (tid < N_CLASSES) out[g * N_CLASSES + tid] = s[tid] + bc[tid];
}

// ---------------------------------------------------------------
extern "C" void kernel_launch(void* const* d_in, const int* in_sizes, int n_in,
                              void* d_out, int out_size) {
    const float* x       = (const float*)d_in[0];
    const int*   e_src   = (const int*)d_in[1];
    const int*   e_dst   = (const int*)d_in[2];
    const int*   batch   = (const int*)d_in[3];
    const float* W0 = (const float*)d_in[4];  const float* b0 = (const float*)d_in[5];
    const float* W1 = (const float*)d_in[6];  const float* b1 = (const float*)d_in[7];
    const float* W2 = (const float*)d_in[8];  const float* b2 = (const float*)d_in[9];
    const float* Wc = (const float*)d_in[10]; const float* bc = (const float*)d_in[11];
    float* out = (float*)d_out;

    const int NB_N  = (N_NODES + 255) / 256;
    const int NB_E  = (N_EDGES + 255) / 256;
    const int NB_NW = (N_NODES * 32 + 255) / 256;
    const int NB_ND = (N_NODES * D + 255) / 256;
    const int gemm_grid = (N_NODES + M_BLK - 1) / M_BLK;   // 1563

    static cudaStream_t s2 = nullptr;
    static cudaEvent_t evFork = nullptr, evJoin = nullptr;
    if (s2 == nullptr) {
        cudaStreamCreate(&s2);
        cudaEventCreateWithFlags(&evFork, cudaEventDisableTiming);
        cudaEventCreateWithFlags(&evJoin, cudaEventDisableTiming);
    }

    // ---- fork: CSR build on s2  ||  cvt_x + layer-0 GEMM on main stream ----
    cudaEventRecord(evFork, 0);
    cudaStreamWaitEvent(s2, evFork, 0);

    k_init<<<NB_N, 256, 0, s2>>>();
    k_count_deg<<<NB_E, 256, 0, s2>>>(e_dst);
    k_scan1<<<N_SCANBLK, SCAN_B, 0, s2>>>();
    k_scan2<<<1, 256, 0, s2>>>();
    k_scan3<<<NB_N, 256, 0, s2>>>(batch);
    k_fill<<<NB_E, 256, 0, s2>>>(e_src, e_dst);

    k_cvt_x<<<NB_ND, 256>>>(x);
    k_gemm_tc<<<gemm_grid, 256>>>(W0);

    cudaEventRecord(evJoin, s2);
    cudaStreamWaitEvent(0, evJoin, 0);

    // ---- layer 0 aggregation ----
    k_gather<0><<<NB_NW, 256>>>(b0, nullptr);
    // ---- layer 1 ----
    k_gemm_tc<<<gemm_grid, 256>>>(W1);
    k_gather<0><<<NB_NW, 256>>>(b1, nullptr);
    // ---- layer 2 (fused mean-pool) ----
    k_gemm_tc<<<gemm_grid, 256>>>(W2);
    k_gather<1><<<NB_NW, 256>>>(b2, batch);

    // ---- classifier ----
    k_classify<<<N_GRAPHS, 128>>>(Wc, bc, out);
}